// round 15
// baseline (speedup 1.0000x reference)
#include <cuda_runtime.h>

#define NI 16384          // inputs per batch row
#define ND 65536          // detectors
#define KK 32             // members per detector (== warp size)
#define BB 32             // batch
#define NPAIR (BB / 2)    // 16 batch pairs
#define NSUB 9            // detector slices per pair
#define NCTA (NPAIR * NSUB)          // 144 CTAs: one wave on 148 SMs
#define ROWS_PER_SUB ((ND + NSUB - 1) / NSUB)   // 7282
#define THREADS 1024
#define WARPS (THREADS / 32)         // 32
#define SMEM_BYTES (NI * 8)          // 128KB: uint2 {keyA, keyB} per input

// Global scratch (allocation-free rule; zero-initialized at module load).
// spike(b,i) <=> wins(b,i) == memberships(i): each detector contributes one
// winner slot + K-1 loser slots, so stat = M - W. Duplicate ids and exact
// value ties preserved (winner = lowest max slot), matching jnp.argmax.
// rel_err 0.0 across R6-R14 with this identity.
// Invariant at kernel_launch entry: g_M == 0 and g_W == 0 (finalize resets
// both; statics start zeroed), so the launch is replay-deterministic.
__device__ unsigned g_M[NI];
__device__ unsigned g_W[BB * NI];

// Order-preserving float -> unsigned key: x >= y (as floats) iff
// key(x) >= key(y) as unsigned. Equal floats -> equal keys.
__device__ __forceinline__ unsigned f32_order_key(unsigned u) {
    return u ^ (((int)u >> 31) | 0x80000000u);
}

// Single-wave layout: 144 CTAs = 16 batch-pairs x 9 detector slices.
// One CTA = one batch pair x ~7282 detector rows; per-SM serialized work
// drops from 4 tiles (wave quantization) to 1 long tile, and the smem
// prologue runs once per SM instead of 4x.
// Mainloop = R12's proven split-depth pipeline: det ids prefetched TWO
// iterations ahead (LDG), gathers ONE ahead (LDS on ids loaded a full
// iteration earlier). Membership histogram inline: a row is counted by the
// CTA whose pair == (row & 15) -> exactly once globally; the condition is
// warp-uniform (row stride 32 == 0 mod 16).
__global__ void __launch_bounds__(THREADS, 1) winner_kernel(
    const float* __restrict__ x,
    const int*   __restrict__ det)
{
    extern __shared__ uint2 xs2[];               // 128KB: {keyA, keyB}

    const int tid  = threadIdx.x;
    const int pair = blockIdx.x & (NPAIR - 1);  // 0..15
    const int sub  = blockIdx.x >> 4;           // 0..8
    const int b0   = pair * 2;

    // Prologue: precompute order keys for both rows (coalesced loads).
    const float* rowA = x + (size_t)b0 * NI;
    const float* rowB = rowA + NI;
    #pragma unroll
    for (int i = tid; i < NI; i += THREADS) {
        unsigned ka = f32_order_key(__float_as_uint(__ldg(rowA + i)));
        unsigned kb = f32_order_key(__float_as_uint(__ldg(rowB + i)));
        xs2[i] = make_uint2(ka, kb);
    }
    __syncthreads();

    const int lane = tid & 31;
    const int warp = tid >> 5;
    const unsigned lt_mask = (1u << lane) - 1u;
    unsigned* WA = g_W + (size_t)b0 * NI;
    unsigned* WB = WA + NI;

    // This CTA's detector row range [r0, r1); warp handles rows
    // r0 + warp + 32*i (per-iter det load = 128B, fully coalesced).
    const int r0 = sub * ROWS_PER_SUB;
    const int r1 = min(ND, r0 + ROWS_PER_SUB);
    const int n  = (r1 - r0 - warp + 31) >> 5;   // per-warp trip count
    const bool count_m = (((r0 + warp) & (NPAIR - 1)) == pair); // warp-const

    const int* dbase = det + (size_t)(r0 + warp) * KK + lane;
    #define ROWSTRIDE (32 * KK)                  // 32 rows per iter step

    // Pipeline prime: ids for iters 0 and 1, gather for iter 0.
    int   id_c = __ldg(dbase);
    int   id_n = (n > 1) ? __ldg(dbase + ROWSTRIDE) : 0;
    uint2 p_c  = xs2[id_c];

    #pragma unroll 4
    for (int i = 0; i < n; i++) {
        // LDG two ahead; LDS one ahead (id loaded a full iteration ago).
        int id_f = 0;
        if (i + 2 < n) id_f = __ldg(dbase + (i + 2) * ROWSTRIDE);
        uint2 p_n = make_uint2(0u, 0u);
        if (i + 1 < n) p_n = xs2[id_n];

        // Inline membership histogram (each det row exactly once globally).
        if (count_m)
            atomicAdd(&g_M[id_c], 1u);           // spread REDG

        unsigned mA = __reduce_max_sync(0xffffffffu, p_c.x);
        unsigned mB = __reduce_max_sync(0xffffffffu, p_c.y);
        unsigned balA = __ballot_sync(0xffffffffu, p_c.x == mA);
        unsigned balB = __ballot_sync(0xffffffffu, p_c.y == mB);
        // winner = lowest lane achieving max (jnp.argmax tie-break);
        // one fire-and-forget gmem RED.ADD per (detector, batch).
        if (p_c.x == mA && (balA & lt_mask) == 0u) atomicAdd(WA + id_c, 1u);
        if (p_c.y == mB && (balB & lt_mask) == 0u) atomicAdd(WB + id_c, 1u);

        id_c = id_n; id_n = id_f; p_c = p_n;
    }
    #undef ROWSTRIDE
}

// Finalize: 1024 blocks x 512 threads; block j owns 16 columns for ALL 32
// batches (one element per thread; consecutive tids -> consecutive columns,
// coalesced). g_M[col] is read only inside its owning block, so after
// __syncthreads() the block resets it. g_W reset inline (own address).
__global__ void __launch_bounds__(512) finalize_kernel(float* __restrict__ out) {
    const int col = blockIdx.x * 16 + (threadIdx.x & 15);
    const int b   = threadIdx.x >> 4;            // 0..31
    const int idx = b * NI + col;
    out[idx] = (g_W[idx] == g_M[col]) ? 1.0f : 0.0f;
    g_W[idx] = 0u;
    __syncthreads();
    if (threadIdx.x < 16)
        g_M[blockIdx.x * 16 + threadIdx.x] = 0u;
}

extern "C" void kernel_launch(void* const* d_in, const int* in_sizes, int n_in,
                              void* d_out, int out_size) {
    const float* x   = (const float*)d_in[0];   // [32, 16384] f32
    const int*   det = (const int*)d_in[1];     // [65536, 32] i32
    float*       out = (float*)d_out;           // [32, 16384] f32

    (void)in_sizes; (void)n_in; (void)out_size;

    cudaFuncSetAttribute(winner_kernel,
                         cudaFuncAttributeMaxDynamicSharedMemorySize,
                         SMEM_BYTES);

    // 1) Winner counting + inline membership histogram (needs M=W=0,
    //    guaranteed by the previous finalize / static zero-init).
    winner_kernel<<<NCTA, THREADS, SMEM_BYTES>>>(x, det);
    // 2) spike = (wins == memberships); resets W and M for the next call.
    finalize_kernel<<<NI / 16, 512>>>(out);
}

// round 16
// speedup vs baseline: 1.0329x; 1.0329x over previous
#include <cuda_runtime.h>

#define NI 16384          // inputs per batch row
#define ND 65536          // detectors
#define KK 32             // members per detector (== warp size)
#define BB 32             // batch
#define NCHUNK 32         // detector tiles
#define DET_PER_CTA (ND / NCHUNK)   // 2048
#define THREADS 1024
#define WARPS (THREADS / 32)        // 32
#define DET_PER_WARP (DET_PER_CTA / WARPS)  // 64
#define SMEM_BYTES (NI * 8)         // 128KB: uint2 {keyA, keyB} per input
#define NPAIR (BB / 2)              // 16

// Global scratch (allocation-free rule; zero-initialized at module load).
// spike(b,i) <=> wins(b,i) == memberships(i): each detector contributes one
// winner slot + K-1 loser slots, so stat = M - W. Duplicate ids and exact
// value ties preserved (winner = lowest max slot), matching jnp.argmax.
// rel_err 0.0 across R6-R15 with this identity.
// Invariant at kernel_launch entry: g_M == 0 and g_W == 0 (finalize resets
// both; statics start zeroed), so the launch is replay-deterministic.
__device__ unsigned g_M[NI];
__device__ unsigned g_W[BB * NI];

// Order-preserving float -> unsigned key: x >= y (as floats) iff
// key(x) >= key(y) as unsigned. Equal floats -> equal keys.
__device__ __forceinline__ unsigned f32_order_key(unsigned u) {
    return u ^ (((int)u >> 31) | 0x80000000u);
}

// R12's winner kernel (best measured: ~54.3us). One CTA = one detector
// tile x one batch pair. One LDS.64 gather serves both batches; the winner
// lane fires a fire-and-forget gmem RED.ADD. Membership histogram built
// inline: rows counted when (i & 15) == pair -> exactly once globally.
// Depth-2 software pipeline: det ids prefetched TWO iterations ahead (LDG),
// gathers ONE ahead (LDS on ids loaded a full iteration earlier), so the
// LDS never issues back-to-back with its producing LDG and the reduce
// never waits on a fresh LDS.
__global__ void __launch_bounds__(THREADS, 1) winner_kernel(
    const float* __restrict__ x,
    const int*   __restrict__ det)
{
    extern __shared__ uint2 xs2[];               // 128KB: {keyA, keyB}

    const int tid   = threadIdx.x;
    const int chunk = blockIdx.x;               // 0..NCHUNK-1
    const int pair  = blockIdx.y;               // 0..NPAIR-1
    const int b0    = pair * 2;

    // Prologue: precompute order keys for both rows (coalesced loads).
    const float* rowA = x + (size_t)b0 * NI;
    const float* rowB = rowA + NI;
    #pragma unroll
    for (int i = tid; i < NI; i += THREADS) {
        unsigned ka = f32_order_key(__float_as_uint(__ldg(rowA + i)));
        unsigned kb = f32_order_key(__float_as_uint(__ldg(rowB + i)));
        xs2[i] = make_uint2(ka, kb);
    }
    __syncthreads();

    const int lane = tid & 31;
    const int warp = tid >> 5;
    const unsigned lt_mask = (1u << lane) - 1u;
    unsigned* WA = g_W + (size_t)b0 * NI;
    unsigned* WB = WA + NI;

    // Warp w owns DET_PER_WARP consecutive detector rows; one row == 128B
    // == one coalesced warp load.
    const int* dbase = det
        + ((size_t)(chunk * DET_PER_CTA + warp * DET_PER_WARP)) * KK + lane;

    // Pipeline prime: ids for iters 0 and 1, gather for iter 0.
    int   id_c = __ldg(dbase);                   // iter 0 id
    int   id_n = __ldg(dbase + KK);              // iter 1 id
    uint2 p_c  = xs2[id_c];                      // iter 0 gather

    #pragma unroll 4
    for (int i = 0; i < DET_PER_WARP; i++) {
        // Prefetch: id two ahead (LDG), gather one ahead (LDS on an id
        // loaded a full iteration ago -> LDG latency already absorbed).
        int id_f = 0;
        if (i + 2 < DET_PER_WARP) id_f = __ldg(dbase + (i + 2) * KK);
        uint2 p_n = make_uint2(0u, 0u);
        if (i + 1 < DET_PER_WARP) p_n = xs2[id_n];

        // Inline membership histogram (exactly-once across pair groups).
        if ((i & (NPAIR - 1)) == pair)
            atomicAdd(&g_M[id_c], 1u);           // spread REDG

        unsigned mA = __reduce_max_sync(0xffffffffu, p_c.x);
        unsigned mB = __reduce_max_sync(0xffffffffu, p_c.y);
        unsigned balA = __ballot_sync(0xffffffffu, p_c.x == mA);
        unsigned balB = __ballot_sync(0xffffffffu, p_c.y == mB);
        // winner = lowest lane achieving max (jnp.argmax tie-break);
        // one fire-and-forget gmem RED.ADD from that lane.
        if (p_c.x == mA && (balA & lt_mask) == 0u) atomicAdd(WA + id_c, 1u);
        if (p_c.y == mB && (balB & lt_mask) == 0u) atomicAdd(WB + id_c, 1u);

        id_c = id_n; id_n = id_f; p_c = p_n;
    }
}

// R13's finalize (best measured: ~5.5us). 1024 blocks x 512 threads; block
// j owns 16 columns for ALL 32 batches (one element per thread; consecutive
// tids -> consecutive columns, coalesced). g_M[col] is read only inside its
// owning block, so after __syncthreads() the block resets it. g_W reset
// inline (own address). Two-launch total.
__global__ void __launch_bounds__(512) finalize_kernel(float* __restrict__ out) {
    const int col = blockIdx.x * 16 + (threadIdx.x & 15);
    const int b   = threadIdx.x >> 4;            // 0..31
    const int idx = b * NI + col;
    out[idx] = (g_W[idx] == g_M[col]) ? 1.0f : 0.0f;
    g_W[idx] = 0u;
    __syncthreads();
    if (threadIdx.x < 16)
        g_M[blockIdx.x * 16 + threadIdx.x] = 0u;
}

extern "C" void kernel_launch(void* const* d_in, const int* in_sizes, int n_in,
                              void* d_out, int out_size) {
    const float* x   = (const float*)d_in[0];   // [32, 16384] f32
    const int*   det = (const int*)d_in[1];     // [65536, 32] i32
    float*       out = (float*)d_out;           // [32, 16384] f32

    (void)in_sizes; (void)n_in; (void)out_size;

    cudaFuncSetAttribute(winner_kernel,
                         cudaFuncAttributeMaxDynamicSharedMemorySize,
                         SMEM_BYTES);

    // 1) Winner counting + inline membership histogram (needs M=W=0,
    //    guaranteed by the previous finalize / static zero-init).
    dim3 grid(NCHUNK, NPAIR);
    winner_kernel<<<grid, THREADS, SMEM_BYTES>>>(x, det);
    // 2) spike = (wins == memberships); resets W and M for the next call.
    finalize_kernel<<<NI / 16, 512>>>(out);
}